// round 1
// baseline (speedup 1.0000x reference)
#include <cuda_runtime.h>
#include <cuda_bf16.h>
#include <cstdint>

#define Bq 4
#define Cq 64
#define Hq 128
#define Wq 128
#define HWq (Hq*Wq)
#define CHWq (Cq*HWq)
#define KK 7
#define TAPS 49

// scratch buffers (allocation-free rule: __device__ globals)
__device__ float g_buf1[Bq*Cq*Hq*Wq];   // 16 MB
__device__ float g_buf2[Bq*Cq*Hq*Wq];   // 16 MB
__device__ float g_buf3[Bq*Cq*Hq*Wq];   // 16 MB (feat)
__device__ float g_lp  [Bq*TAPS*Hq*Wq]; // 12.25 MB

#define CI_CHUNK 8
#define TILE 16

// ---------------------------------------------------------------------------
// conv3x3, 64->64 channels. One thread = one output pixel, all 64 output
// channels as 32 packed f32x2 accumulators. Weights staged in SMEM as
// [ci][tap][co] so LDS.128 feeds pairs directly into fma.rn.f32x2.
// ---------------------------------------------------------------------------
template<bool RELU_IN, bool RELU_OUT, bool MUL>
__global__ __launch_bounds__(256, 2)
void conv3x3_kernel(const float* __restrict__ in, const float* __restrict__ wgt,
                    const float* __restrict__ bias, const float* __restrict__ mul,
                    float* __restrict__ out)
{
    __shared__ float s_in[CI_CHUNK][18][20];
    __shared__ float s_w[CI_CHUNK*9*64];

    const int b  = blockIdx.z;
    const int x0 = blockIdx.x * TILE;
    const int y0 = blockIdx.y * TILE;
    const int tid = threadIdx.x;
    const int tx = tid & 15, ty = tid >> 4;

    const float* inb = in + b*CHWq;

    unsigned long long acc[32];
#pragma unroll
    for (int i = 0; i < 32; i++) acc[i] = 0ULL;  // (+0.f, +0.f)

    for (int cc = 0; cc < Cq; cc += CI_CHUNK) {
        // stage weights: s_w[(ci_l*9+tap)*64 + co] = wgt[co][cc+ci_l][tap]
        for (int i = tid; i < CI_CHUNK*9*64; i += 256) {
            int co  = i & 63;
            int rem = i >> 6;           // ci_l*9 + tap
            int ci_l = rem / 9;
            int tap  = rem - ci_l*9;
            s_w[i] = wgt[(co*Cq + cc + ci_l)*9 + tap];
        }
        // stage input tile (18x18 with halo 1, zero padded)
        for (int i = tid; i < CI_CHUNK*18*18; i += 256) {
            int ci_l = i / 324;
            int r    = (i - ci_l*324) / 18;
            int c    = i - ci_l*324 - r*18;
            int gy = y0 + r - 1, gx = x0 + c - 1;
            float v = 0.f;
            if (gy >= 0 && gy < Hq && gx >= 0 && gx < Wq) {
                v = inb[(cc+ci_l)*HWq + gy*Wq + gx];
                if (RELU_IN) v = fmaxf(v, 0.f);
            }
            s_in[ci_l][r][c] = v;
        }
        __syncthreads();

#pragma unroll
        for (int ci_l = 0; ci_l < CI_CHUNK; ci_l++) {
            float v[9];
#pragma unroll
            for (int dy = 0; dy < 3; dy++)
#pragma unroll
                for (int dx = 0; dx < 3; dx++)
                    v[dy*3+dx] = s_in[ci_l][ty+dy][tx+dx];
#pragma unroll
            for (int tap = 0; tap < 9; tap++) {
                unsigned int vi = __float_as_uint(v[tap]);
                unsigned long long vd;
                asm("mov.b64 %0, {%1, %1};" : "=l"(vd) : "r"(vi));
                const ulonglong2* wr =
                    (const ulonglong2*)(s_w + (ci_l*9 + tap)*64);
#pragma unroll
                for (int j = 0; j < 16; j++) {
                    ulonglong2 wp = wr[j];
                    asm("fma.rn.f32x2 %0, %1, %2, %0;"
                        : "+l"(acc[2*j])   : "l"(wp.x), "l"(vd));
                    asm("fma.rn.f32x2 %0, %1, %2, %0;"
                        : "+l"(acc[2*j+1]) : "l"(wp.y), "l"(vd));
                }
            }
        }
        __syncthreads();
    }

    const int y = y0 + ty, x = x0 + tx;
    float*       outp = out + b*CHWq + y*Wq + x;
    const float* mulp = mul + b*CHWq + y*Wq + x;  // unused unless MUL
#pragma unroll
    for (int i = 0; i < 32; i++) {
        unsigned int u0, u1;
        asm("mov.b64 {%0, %1}, %2;" : "=r"(u0), "=r"(u1) : "l"(acc[i]));
        int co0 = 2*i, co1 = 2*i + 1;
        float r0 = __uint_as_float(u0) + __ldg(bias + co0);
        float r1 = __uint_as_float(u1) + __ldg(bias + co1);
        if (RELU_OUT) { r0 = fmaxf(r0, 0.f); r1 = fmaxf(r1, 0.f); }
        if (MUL) { r0 *= mulp[co0*HWq]; r1 *= mulp[co1*HWq]; }
        outp[co0*HWq] = r0;
        outp[co1*HWq] = r1;
    }
}

// ---------------------------------------------------------------------------
// local_filter_path: conv1x1(64->64) -> relu -> conv1x1(64->49) -> normalize,
// all fused. One thread = one pixel.
// ---------------------------------------------------------------------------
__global__ __launch_bounds__(256, 1)
void lp_kernel(const float* __restrict__ kf,
               const float* __restrict__ w1, const float* __restrict__ b1,
               const float* __restrict__ w2, const float* __restrict__ b2,
               float* __restrict__ lp)
{
    __shared__ float s_w1[64*64];   // [ci][co]
    __shared__ float s_w2[64*52];   // [ci][k], row padded to 52
    __shared__ float s_b1[64];
    __shared__ float s_b2[49];
    const int tid = threadIdx.x;

    for (int i = tid; i < 64*64; i += 256) {
        int ci = i >> 6, co = i & 63;
        s_w1[i] = w1[co*64 + ci];
    }
    for (int i = tid; i < 64*49; i += 256) {
        int ci = i / 49, k = i - ci*49;
        s_w2[ci*52 + k] = w2[k*64 + ci];
    }
    if (tid < 64) s_b1[tid] = b1[tid];
    if (tid < 49) s_b2[tid] = b2[tid];
    __syncthreads();

    const int p  = blockIdx.x*256 + tid;   // 0..B*HW-1
    const int b  = p >> 14;                // /HW
    const int hw = p & (HWq-1);
    const float* kfp = kf + b*CHWq + hw;

    float h[64];
#pragma unroll
    for (int c = 0; c < 64; c++) h[c] = s_b1[c];
    for (int ci = 0; ci < 64; ci++) {
        float xv = kfp[ci*HWq];
#pragma unroll
        for (int co = 0; co < 64; co++)
            h[co] = fmaf(s_w1[ci*64 + co], xv, h[co]);
    }
#pragma unroll
    for (int c = 0; c < 64; c++) h[c] = fmaxf(h[c], 0.f);

    float o[TAPS];
#pragma unroll
    for (int k = 0; k < TAPS; k++) o[k] = s_b2[k];
    for (int ci = 0; ci < 64; ci++) {
        float hv = h[ci];
#pragma unroll
        for (int k = 0; k < TAPS; k++)
            o[k] = fmaf(s_w2[ci*52 + k], hv, o[k]);
    }
    float m = 0.f;
#pragma unroll
    for (int k = 0; k < TAPS; k++) m += o[k];
    m *= (1.0f/49.0f);

    float* lpp = lp + b*TAPS*HWq + hw;
#pragma unroll
    for (int k = 0; k < TAPS; k++)
        lpp[k*HWq] = o[k] - m + (1.0f/49.0f);
}

// ---------------------------------------------------------------------------
// dynamic 7x7 local conv + residual: out = x + sum_taps feat_shift * lp[tap].
// Per thread: pixel kernel (49 regs), loop over 64 channels with SMEM tile.
// ---------------------------------------------------------------------------
__global__ __launch_bounds__(256, 2)
void local_conv_kernel(const float* __restrict__ x, const float* __restrict__ feat,
                       const float* __restrict__ lp, float* __restrict__ out)
{
    __shared__ float s_f[22][24];
    const int b  = blockIdx.z;
    const int x0 = blockIdx.x * TILE;
    const int y0 = blockIdx.y * TILE;
    const int tid = threadIdx.x;
    const int tx = tid & 15, ty = tid >> 4;
    const int y = y0 + ty, xx = x0 + tx;

    float kl[TAPS];
    const float* lpp = lp + b*TAPS*HWq + y*Wq + xx;
#pragma unroll
    for (int k = 0; k < TAPS; k++) kl[k] = lpp[k*HWq];

    const float* fb = feat + b*CHWq;
    const float* xb = x    + b*CHWq;
    float*       ob = out  + b*CHWq;

    for (int c = 0; c < Cq; c++) {
        __syncthreads();
        for (int i = tid; i < 22*22; i += 256) {
            int r  = i / 22;
            int cc = i - r*22;
            int gy = y0 + r - 3, gx = x0 + cc - 3;
            float v = 0.f;
            if (gy >= 0 && gy < Hq && gx >= 0 && gx < Wq)
                v = fb[c*HWq + gy*Wq + gx];
            s_f[r][cc] = v;
        }
        __syncthreads();
        float acc = 0.f;
#pragma unroll
        for (int dy = 0; dy < KK; dy++)
#pragma unroll
            for (int dx = 0; dx < KK; dx++)
                acc = fmaf(s_f[ty+dy][tx+dx], kl[dy*KK+dx], acc);
        ob[c*HWq + y*Wq + xx] = xb[c*HWq + y*Wq + xx] + acc;
    }
}

// ---------------------------------------------------------------------------
extern "C" void kernel_launch(void* const* d_in, const int* in_sizes, int n_in,
                              void* d_out, int out_size)
{
    const float* x   = (const float*)d_in[0];
    const float* kf  = (const float*)d_in[1];
    const float* fw1 = (const float*)d_in[2];
    const float* fb1 = (const float*)d_in[3];
    const float* fw2 = (const float*)d_in[4];
    const float* fb2 = (const float*)d_in[5];
    const float* mw1 = (const float*)d_in[6];
    const float* mb1 = (const float*)d_in[7];
    const float* mw2 = (const float*)d_in[8];
    const float* mb2 = (const float*)d_in[9];
    const float* lw1 = (const float*)d_in[10];
    const float* lb1 = (const float*)d_in[11];
    const float* lw2 = (const float*)d_in[12];
    const float* lb2 = (const float*)d_in[13];
    float* out = (float*)d_out;

    float *b1p, *b2p, *b3p, *lpp;
    cudaGetSymbolAddress((void**)&b1p, g_buf1);
    cudaGetSymbolAddress((void**)&b2p, g_buf2);
    cudaGetSymbolAddress((void**)&b3p, g_buf3);
    cudaGetSymbolAddress((void**)&lpp, g_lp);

    dim3 cgrid(Wq/TILE, Hq/TILE, Bq);   // 8,8,4
    dim3 cblk(256);

    // feature_path: relu -> conv -> relu -> conv
    conv3x3_kernel<true,  true,  false><<<cgrid, cblk>>>(x,   fw1, fb1, nullptr, b1p);
    conv3x3_kernel<false, false, false><<<cgrid, cblk>>>(b1p, fw2, fb2, nullptr, b2p); // fp
    // multiplicative_path: conv -> relu -> conv, fused with fp multiply -> feat
    conv3x3_kernel<false, true,  false><<<cgrid, cblk>>>(kf,  mw1, mb1, nullptr, b1p);
    conv3x3_kernel<false, false, true ><<<cgrid, cblk>>>(b1p, mw2, mb2, b2p,     b3p); // feat
    // local_filter_path (independent): 1x1 -> relu -> 1x1 -> normalize
    lp_kernel<<<(Bq*HWq)/256, cblk>>>(kf, lw1, lb1, lw2, lb2, lpp);
    // dynamic local conv + residual
    local_conv_kernel<<<cgrid, cblk>>>(x, b3p, lpp, out);
}

// round 2
// speedup vs baseline: 1.4628x; 1.4628x over previous
#include <cuda_runtime.h>
#include <cuda_bf16.h>
#include <cstdint>

#define Bq 4
#define Cq 64
#define Hq 128
#define Wq 128
#define HWq (Hq*Wq)
#define CHWq (Cq*HWq)
#define KK 7
#define TAPS 49

// scratch buffers (allocation-free rule: __device__ globals)
__device__ float g_buf1[Bq*Cq*Hq*Wq];   // 16 MB
__device__ float g_buf2[Bq*Cq*Hq*Wq];   // 16 MB
__device__ float g_buf3[Bq*Cq*Hq*Wq];   // 16 MB (feat)
__device__ float g_lp  [Bq*TAPS*Hq*Wq]; // 12.25 MB

#define CI_CHUNK 8
#define TILE 16
#define SROW 24   // padded s_in row stride (floats), 16B-aligned rows

// ---------------------------------------------------------------------------
// conv3x3, 64->64 channels. Register-blocked: each thread computes 4
// contiguous x-pixels x 16 output channels (8 f32x2 per pixel).
// 256 threads = 16x16 pixel tile x 4 channel groups.
// Weights staged in SMEM as [ci][tap][co]; weight LDS.128 are warp-uniform
// (broadcast). Inputs loaded as 2x LDS.128 per (ci,dy), reused across dx taps.
// ---------------------------------------------------------------------------
template<bool RELU_IN, bool RELU_OUT, bool MUL>
__global__ __launch_bounds__(256, 2)
void conv3x3_kernel(const float* __restrict__ in, const float* __restrict__ wgt,
                    const float* __restrict__ bias, const float* __restrict__ mul,
                    float* __restrict__ out)
{
    __shared__ float s_in[CI_CHUNK][18][SROW];
    __shared__ float s_w[CI_CHUNK*9*64];

    const int b  = blockIdx.z;
    const int x0 = blockIdx.x * TILE;
    const int y0 = blockIdx.y * TILE;
    const int tid = threadIdx.x;
    const int cg  = tid >> 6;          // channel group 0..3 (16 ch each)
    const int pg  = tid & 63;          // pixel group
    const int py  = pg >> 2;           // 0..15
    const int px4 = (pg & 3) << 2;     // 0,4,8,12

    const float* inb = in + b*CHWq;

    unsigned long long acc[32];        // [px][k] : px*8 + k, k = f32x2 pair
#pragma unroll
    for (int i = 0; i < 32; i++) acc[i] = 0ULL;

    for (int cc = 0; cc < Cq; cc += CI_CHUNK) {
        // stage weights: s_w[(ci_l*9+tap)*64 + co] = wgt[co][cc+ci_l][tap]
        for (int i = tid; i < CI_CHUNK*9*64; i += 256) {
            int co  = i & 63;
            int rem = i >> 6;           // ci_l*9 + tap
            int ci_l = rem / 9;
            int tap  = rem - ci_l*9;
            s_w[i] = wgt[(co*Cq + cc + ci_l)*9 + tap];
        }
        // stage input tile (18x18 with halo 1, zero padded)
        for (int i = tid; i < CI_CHUNK*18*18; i += 256) {
            int ci_l = i / 324;
            int r    = (i - ci_l*324) / 18;
            int c    = i - ci_l*324 - r*18;
            int gy = y0 + r - 1, gx = x0 + c - 1;
            float v = 0.f;
            if (gy >= 0 && gy < Hq && gx >= 0 && gx < Wq) {
                v = inb[(cc+ci_l)*HWq + gy*Wq + gx];
                if (RELU_IN) v = fmaxf(v, 0.f);
            }
            s_in[ci_l][r][c] = v;
        }
        __syncthreads();

#pragma unroll
        for (int ci_l = 0; ci_l < CI_CHUNK; ci_l++) {
#pragma unroll
            for (int dy = 0; dy < 3; dy++) {
                // 8 contiguous input floats (cols px4..px4+7), 2x LDS.128
                const float4* ip =
                    (const float4*)&s_in[ci_l][py + dy][px4];
                float4 a0 = ip[0];
                float4 a1 = ip[1];
                // duplicate cols px4..px4+5 into f32x2 registers
                unsigned long long d[6];
                {
                    unsigned int u;
                    u = __float_as_uint(a0.x); asm("mov.b64 %0,{%1,%1};" : "=l"(d[0]) : "r"(u));
                    u = __float_as_uint(a0.y); asm("mov.b64 %0,{%1,%1};" : "=l"(d[1]) : "r"(u));
                    u = __float_as_uint(a0.z); asm("mov.b64 %0,{%1,%1};" : "=l"(d[2]) : "r"(u));
                    u = __float_as_uint(a0.w); asm("mov.b64 %0,{%1,%1};" : "=l"(d[3]) : "r"(u));
                    u = __float_as_uint(a1.x); asm("mov.b64 %0,{%1,%1};" : "=l"(d[4]) : "r"(u));
                    u = __float_as_uint(a1.y); asm("mov.b64 %0,{%1,%1};" : "=l"(d[5]) : "r"(u));
                }
#pragma unroll
                for (int dx = 0; dx < 3; dx++) {
                    const ulonglong2* wv = (const ulonglong2*)
                        (s_w + (ci_l*9 + dy*3 + dx)*64 + (cg << 4));
                    ulonglong2 w0 = wv[0], w1 = wv[1], w2 = wv[2], w3 = wv[3];
                    unsigned long long w[8] =
                        { w0.x, w0.y, w1.x, w1.y, w2.x, w2.y, w3.x, w3.y };
#pragma unroll
                    for (int i = 0; i < 4; i++) {
                        unsigned long long vd = d[i + dx];
#pragma unroll
                        for (int k = 0; k < 8; k++) {
                            asm("fma.rn.f32x2 %0, %1, %2, %0;"
                                : "+l"(acc[i*8 + k]) : "l"(w[k]), "l"(vd));
                        }
                    }
                }
            }
        }
        __syncthreads();
    }

    // epilogue: 16 channels x 4 px per thread; float4 stores
    const int y = y0 + py;
    const int xbase = x0 + px4;
    const int co0 = cg << 4;
    float*       outp = out + b*CHWq + y*Wq + xbase;
    const float* mulp = mul + b*CHWq + y*Wq + xbase;  // unused unless MUL
#pragma unroll
    for (int k = 0; k < 8; k++) {
        float lo[4], hi[4];
#pragma unroll
        for (int i = 0; i < 4; i++) {
            unsigned int u0, u1;
            asm("mov.b64 {%0,%1}, %2;" : "=r"(u0), "=r"(u1) : "l"(acc[i*8 + k]));
            lo[i] = __uint_as_float(u0);
            hi[i] = __uint_as_float(u1);
        }
        int cA = co0 + 2*k, cB = cA + 1;
        float bA = __ldg(bias + cA), bB = __ldg(bias + cB);
        float4 ra, rb;
        ra.x = lo[0]+bA; ra.y = lo[1]+bA; ra.z = lo[2]+bA; ra.w = lo[3]+bA;
        rb.x = hi[0]+bB; rb.y = hi[1]+bB; rb.z = hi[2]+bB; rb.w = hi[3]+bB;
        if (RELU_OUT) {
            ra.x=fmaxf(ra.x,0.f); ra.y=fmaxf(ra.y,0.f); ra.z=fmaxf(ra.z,0.f); ra.w=fmaxf(ra.w,0.f);
            rb.x=fmaxf(rb.x,0.f); rb.y=fmaxf(rb.y,0.f); rb.z=fmaxf(rb.z,0.f); rb.w=fmaxf(rb.w,0.f);
        }
        if (MUL) {
            float4 ma = *(const float4*)(mulp + cA*HWq);
            float4 mb = *(const float4*)(mulp + cB*HWq);
            ra.x*=ma.x; ra.y*=ma.y; ra.z*=ma.z; ra.w*=ma.w;
            rb.x*=mb.x; rb.y*=mb.y; rb.z*=mb.z; rb.w*=mb.w;
        }
        *(float4*)(outp + cA*HWq) = ra;
        *(float4*)(outp + cB*HWq) = rb;
    }
}

// ---------------------------------------------------------------------------
// local_filter_path: conv1x1(64->64) -> relu -> conv1x1(64->49) -> normalize,
// all fused. One thread = one pixel.
// ---------------------------------------------------------------------------
__global__ __launch_bounds__(256, 1)
void lp_kernel(const float* __restrict__ kf,
               const float* __restrict__ w1, const float* __restrict__ b1,
               const float* __restrict__ w2, const float* __restrict__ b2,
               float* __restrict__ lp)
{
    __shared__ float s_w1[64*64];   // [ci][co]
    __shared__ float s_w2[64*52];   // [ci][k], row padded to 52
    __shared__ float s_b1[64];
    __shared__ float s_b2[49];
    const int tid = threadIdx.x;

    for (int i = tid; i < 64*64; i += 256) {
        int ci = i >> 6, co = i & 63;
        s_w1[i] = w1[co*64 + ci];
    }
    for (int i = tid; i < 64*49; i += 256) {
        int ci = i / 49, k = i - ci*49;
        s_w2[ci*52 + k] = w2[k*64 + ci];
    }
    if (tid < 64) s_b1[tid] = b1[tid];
    if (tid < 49) s_b2[tid] = b2[tid];
    __syncthreads();

    const int p  = blockIdx.x*256 + tid;   // 0..B*HW-1
    const int b  = p >> 14;                // /HW
    const int hw = p & (HWq-1);
    const float* kfp = kf + b*CHWq + hw;

    float h[64];
#pragma unroll
    for (int c = 0; c < 64; c++) h[c] = s_b1[c];
    for (int ci = 0; ci < 64; ci++) {
        float xv = kfp[ci*HWq];
#pragma unroll
        for (int co = 0; co < 64; co++)
            h[co] = fmaf(s_w1[ci*64 + co], xv, h[co]);
    }
#pragma unroll
    for (int c = 0; c < 64; c++) h[c] = fmaxf(h[c], 0.f);

    float o[TAPS];
#pragma unroll
    for (int k = 0; k < TAPS; k++) o[k] = s_b2[k];
    for (int ci = 0; ci < 64; ci++) {
        float hv = h[ci];
#pragma unroll
        for (int k = 0; k < TAPS; k++)
            o[k] = fmaf(s_w2[ci*52 + k], hv, o[k]);
    }
    float m = 0.f;
#pragma unroll
    for (int k = 0; k < TAPS; k++) m += o[k];
    m *= (1.0f/49.0f);

    float* lpp = lp + b*TAPS*HWq + hw;
#pragma unroll
    for (int k = 0; k < TAPS; k++)
        lpp[k*HWq] = o[k] - m + (1.0f/49.0f);
}

// ---------------------------------------------------------------------------
// dynamic 7x7 local conv + residual: out = x + sum_taps feat_shift * lp[tap].
// grid.z = B*4 : each block handles 16 channels (more parallelism, fewer
// serial syncs than the full-64 loop).
// ---------------------------------------------------------------------------
#define LC_CG 4
#define LC_CPB (Cq/LC_CG)   // 16 channels per block
__global__ __launch_bounds__(256, 2)
void local_conv_kernel(const float* __restrict__ x, const float* __restrict__ feat,
                       const float* __restrict__ lp, float* __restrict__ out)
{
    __shared__ float s_f[22][24];
    const int bz = blockIdx.z;
    const int b  = bz >> 2;
    const int c0 = (bz & 3) * LC_CPB;
    const int x0 = blockIdx.x * TILE;
    const int y0 = blockIdx.y * TILE;
    const int tid = threadIdx.x;
    const int tx = tid & 15, ty = tid >> 4;
    const int y = y0 + ty, xx = x0 + tx;

    float kl[TAPS];
    const float* lpp = lp + b*TAPS*HWq + y*Wq + xx;
#pragma unroll
    for (int k = 0; k < TAPS; k++) kl[k] = lpp[k*HWq];

    const float* fb = feat + b*CHWq;
    const float* xb = x    + b*CHWq;
    float*       ob = out  + b*CHWq;

    for (int ci = 0; ci < LC_CPB; ci++) {
        const int c = c0 + ci;
        __syncthreads();
        for (int i = tid; i < 22*22; i += 256) {
            int r  = i / 22;
            int cc = i - r*22;
            int gy = y0 + r - 3, gx = x0 + cc - 3;
            float v = 0.f;
            if (gy >= 0 && gy < Hq && gx >= 0 && gx < Wq)
                v = fb[c*HWq + gy*Wq + gx];
            s_f[r][cc] = v;
        }
        __syncthreads();
        float acc = 0.f;
#pragma unroll
        for (int dy = 0; dy < KK; dy++)
#pragma unroll
            for (int dx = 0; dx < KK; dx++)
                acc = fmaf(s_f[ty+dy][tx+dx], kl[dy*KK+dx], acc);
        ob[c*HWq + y*Wq + xx] = xb[c*HWq + y*Wq + xx] + acc;
    }
}

// ---------------------------------------------------------------------------
extern "C" void kernel_launch(void* const* d_in, const int* in_sizes, int n_in,
                              void* d_out, int out_size)
{
    const float* x   = (const float*)d_in[0];
    const float* kf  = (const float*)d_in[1];
    const float* fw1 = (const float*)d_in[2];
    const float* fb1 = (const float*)d_in[3];
    const float* fw2 = (const float*)d_in[4];
    const float* fb2 = (const float*)d_in[5];
    const float* mw1 = (const float*)d_in[6];
    const float* mb1 = (const float*)d_in[7];
    const float* mw2 = (const float*)d_in[8];
    const float* mb2 = (const float*)d_in[9];
    const float* lw1 = (const float*)d_in[10];
    const float* lb1 = (const float*)d_in[11];
    const float* lw2 = (const float*)d_in[12];
    const float* lb2 = (const float*)d_in[13];
    float* out = (float*)d_out;

    float *b1p, *b2p, *b3p, *lpp;
    cudaGetSymbolAddress((void**)&b1p, g_buf1);
    cudaGetSymbolAddress((void**)&b2p, g_buf2);
    cudaGetSymbolAddress((void**)&b3p, g_buf3);
    cudaGetSymbolAddress((void**)&lpp, g_lp);

    dim3 cgrid(Wq/TILE, Hq/TILE, Bq);   // 8,8,4
    dim3 cblk(256);

    // feature_path: relu -> conv -> relu -> conv
    conv3x3_kernel<true,  true,  false><<<cgrid, cblk>>>(x,   fw1, fb1, nullptr, b1p);
    conv3x3_kernel<false, false, false><<<cgrid, cblk>>>(b1p, fw2, fb2, nullptr, b2p); // fp
    // multiplicative_path: conv -> relu -> conv, fused with fp multiply -> feat
    conv3x3_kernel<false, true,  false><<<cgrid, cblk>>>(kf,  mw1, mb1, nullptr, b1p);
    conv3x3_kernel<false, false, true ><<<cgrid, cblk>>>(b1p, mw2, mb2, b2p,     b3p); // feat
    // local_filter_path (independent): 1x1 -> relu -> 1x1 -> normalize
    lp_kernel<<<(Bq*HWq)/256, cblk>>>(kf, lw1, lb1, lw2, lb2, lpp);
    // dynamic local conv + residual
    dim3 lgrid(Wq/TILE, Hq/TILE, Bq*LC_CG);
    local_conv_kernel<<<lgrid, cblk>>>(x, b3p, lpp, out);
}

// round 3
// speedup vs baseline: 1.4705x; 1.0052x over previous
#include <cuda_runtime.h>
#include <cuda_bf16.h>
#include <cstdint>

#define Bq 4
#define Cq 64
#define Hq 128
#define Wq 128
#define HWq (Hq*Wq)
#define CHWq (Cq*HWq)
#define KK 7
#define TAPS 49

// scratch buffers (allocation-free rule: __device__ globals)
__device__ float g_buf1[Bq*Cq*Hq*Wq];   // 16 MB
__device__ float g_buf2[Bq*Cq*Hq*Wq];   // 16 MB
__device__ float g_buf3[Bq*Cq*Hq*Wq];   // 16 MB (feat)
__device__ float g_lp  [Bq*TAPS*Hq*Wq]; // 12.25 MB

#define CI_CHUNK 8
#define TILE 16
#define SROW 28   // padded s_in row stride (floats); 112B, 16B-aligned rows

// ---------------------------------------------------------------------------
// conv3x3, 64->64 channels. Register-blocked: each thread computes 8
// contiguous x-pixels x 8 output channels (4 f32x2 pairs per pixel).
// 256 threads = 8 channel groups (one per warp, warp-uniform) x 32 pixel
// groups (16 y x 2 x-halves). Per (ci,tap): 2 warp-uniform weight LDS.128
// feed 32 FFMA2; per (ci,dy): 3 input LDS.128 cover 8 output pixels.
// ---------------------------------------------------------------------------
template<bool RELU_IN, bool RELU_OUT, bool MUL>
__global__ __launch_bounds__(256, 2)
void conv3x3_kernel(const float* __restrict__ in, const float* __restrict__ wgt,
                    const float* __restrict__ bias, const float* __restrict__ mul,
                    float* __restrict__ out)
{
    __shared__ float s_in[CI_CHUNK][18][SROW];
    __shared__ float s_w[CI_CHUNK*9*64];

    const int b  = blockIdx.z;
    const int x0 = blockIdx.x * TILE;
    const int y0 = blockIdx.y * TILE;
    const int tid = threadIdx.x;
    const int cg  = tid >> 5;          // channel group 0..7 (8 ch each), warp-uniform
    const int pg  = tid & 31;          // pixel group
    const int py  = pg >> 1;           // 0..15
    const int px8 = (pg & 1) << 3;     // 0 or 8

    const float* inb = in + b*CHWq;

    unsigned long long acc[32];        // [px][k] : px*4 + k, k = f32x2 pair
#pragma unroll
    for (int i = 0; i < 32; i++) acc[i] = 0ULL;

    for (int cc = 0; cc < Cq; cc += CI_CHUNK) {
        // stage weights: s_w[(ci_l*9+tap)*64 + co] = wgt[co][cc+ci_l][tap]
        for (int i = tid; i < CI_CHUNK*9*64; i += 256) {
            int co  = i & 63;
            int rem = i >> 6;           // ci_l*9 + tap
            int ci_l = rem / 9;
            int tap  = rem - ci_l*9;
            s_w[i] = wgt[(co*Cq + cc + ci_l)*9 + tap];
        }
        // stage input tile (18x18 with halo 1, zero padded)
        for (int i = tid; i < CI_CHUNK*18*18; i += 256) {
            int ci_l = i / 324;
            int r    = (i - ci_l*324) / 18;
            int c    = i - ci_l*324 - r*18;
            int gy = y0 + r - 1, gx = x0 + c - 1;
            float v = 0.f;
            if (gy >= 0 && gy < Hq && gx >= 0 && gx < Wq) {
                v = inb[(cc+ci_l)*HWq + gy*Wq + gx];
                if (RELU_IN) v = fmaxf(v, 0.f);
            }
            s_in[ci_l][r][c] = v;
        }
        __syncthreads();

#pragma unroll
        for (int ci_l = 0; ci_l < CI_CHUNK; ci_l++) {
#pragma unroll
            for (int dy = 0; dy < 3; dy++) {
                // 12 contiguous input floats (cols px8..px8+11), 3x LDS.128
                const float4* ip =
                    (const float4*)&s_in[ci_l][py + dy][px8];
                float4 a0 = ip[0];
                float4 a1 = ip[1];
                float4 a2 = ip[2];
                // duplicate cols px8..px8+9 into f32x2 registers
                unsigned long long d[10];
                {
                    unsigned int u;
                    u = __float_as_uint(a0.x); asm("mov.b64 %0,{%1,%1};" : "=l"(d[0]) : "r"(u));
                    u = __float_as_uint(a0.y); asm("mov.b64 %0,{%1,%1};" : "=l"(d[1]) : "r"(u));
                    u = __float_as_uint(a0.z); asm("mov.b64 %0,{%1,%1};" : "=l"(d[2]) : "r"(u));
                    u = __float_as_uint(a0.w); asm("mov.b64 %0,{%1,%1};" : "=l"(d[3]) : "r"(u));
                    u = __float_as_uint(a1.x); asm("mov.b64 %0,{%1,%1};" : "=l"(d[4]) : "r"(u));
                    u = __float_as_uint(a1.y); asm("mov.b64 %0,{%1,%1};" : "=l"(d[5]) : "r"(u));
                    u = __float_as_uint(a1.z); asm("mov.b64 %0,{%1,%1};" : "=l"(d[6]) : "r"(u));
                    u = __float_as_uint(a1.w); asm("mov.b64 %0,{%1,%1};" : "=l"(d[7]) : "r"(u));
                    u = __float_as_uint(a2.x); asm("mov.b64 %0,{%1,%1};" : "=l"(d[8]) : "r"(u));
                    u = __float_as_uint(a2.y); asm("mov.b64 %0,{%1,%1};" : "=l"(d[9]) : "r"(u));
                }
#pragma unroll
                for (int dx = 0; dx < 3; dx++) {
                    const ulonglong2* wv = (const ulonglong2*)
                        (s_w + (ci_l*9 + dy*3 + dx)*64 + (cg << 3));
                    ulonglong2 w0 = wv[0], w1 = wv[1];
                    unsigned long long w[4] = { w0.x, w0.y, w1.x, w1.y };
#pragma unroll
                    for (int i = 0; i < 8; i++) {
                        unsigned long long vd = d[i + dx];
#pragma unroll
                        for (int k = 0; k < 4; k++) {
                            asm("fma.rn.f32x2 %0, %1, %2, %0;"
                                : "+l"(acc[i*4 + k]) : "l"(w[k]), "l"(vd));
                        }
                    }
                }
            }
        }
        __syncthreads();
    }

    // epilogue: 8 channels x 8 px per thread; float4 stores
    const int y = y0 + py;
    const int xbase = x0 + px8;
    const int co0 = cg << 3;
    float*       outp = out + b*CHWq + y*Wq + xbase;
    const float* mulp = mul + b*CHWq + y*Wq + xbase;  // unused unless MUL
#pragma unroll
    for (int k = 0; k < 4; k++) {
        float lo[8], hi[8];
#pragma unroll
        for (int i = 0; i < 8; i++) {
            unsigned int u0, u1;
            asm("mov.b64 {%0,%1}, %2;" : "=r"(u0), "=r"(u1) : "l"(acc[i*4 + k]));
            lo[i] = __uint_as_float(u0);
            hi[i] = __uint_as_float(u1);
        }
        int cA = co0 + 2*k, cB = cA + 1;
        float bA = __ldg(bias + cA), bB = __ldg(bias + cB);
        float4 ra0, ra1, rb0, rb1;
        ra0.x = lo[0]+bA; ra0.y = lo[1]+bA; ra0.z = lo[2]+bA; ra0.w = lo[3]+bA;
        ra1.x = lo[4]+bA; ra1.y = lo[5]+bA; ra1.z = lo[6]+bA; ra1.w = lo[7]+bA;
        rb0.x = hi[0]+bB; rb0.y = hi[1]+bB; rb0.z = hi[2]+bB; rb0.w = hi[3]+bB;
        rb1.x = hi[4]+bB; rb1.y = hi[5]+bB; rb1.z = hi[6]+bB; rb1.w = hi[7]+bB;
        if (RELU_OUT) {
            ra0.x=fmaxf(ra0.x,0.f); ra0.y=fmaxf(ra0.y,0.f); ra0.z=fmaxf(ra0.z,0.f); ra0.w=fmaxf(ra0.w,0.f);
            ra1.x=fmaxf(ra1.x,0.f); ra1.y=fmaxf(ra1.y,0.f); ra1.z=fmaxf(ra1.z,0.f); ra1.w=fmaxf(ra1.w,0.f);
            rb0.x=fmaxf(rb0.x,0.f); rb0.y=fmaxf(rb0.y,0.f); rb0.z=fmaxf(rb0.z,0.f); rb0.w=fmaxf(rb0.w,0.f);
            rb1.x=fmaxf(rb1.x,0.f); rb1.y=fmaxf(rb1.y,0.f); rb1.z=fmaxf(rb1.z,0.f); rb1.w=fmaxf(rb1.w,0.f);
        }
        if (MUL) {
            float4 ma0 = *(const float4*)(mulp + cA*HWq);
            float4 ma1 = *(const float4*)(mulp + cA*HWq + 4);
            float4 mb0 = *(const float4*)(mulp + cB*HWq);
            float4 mb1 = *(const float4*)(mulp + cB*HWq + 4);
            ra0.x*=ma0.x; ra0.y*=ma0.y; ra0.z*=ma0.z; ra0.w*=ma0.w;
            ra1.x*=ma1.x; ra1.y*=ma1.y; ra1.z*=ma1.z; ra1.w*=ma1.w;
            rb0.x*=mb0.x; rb0.y*=mb0.y; rb0.z*=mb0.z; rb0.w*=mb0.w;
            rb1.x*=mb1.x; rb1.y*=mb1.y; rb1.z*=mb1.z; rb1.w*=mb1.w;
        }
        *(float4*)(outp + cA*HWq)     = ra0;
        *(float4*)(outp + cA*HWq + 4) = ra1;
        *(float4*)(outp + cB*HWq)     = rb0;
        *(float4*)(outp + cB*HWq + 4) = rb1;
    }
}

// ---------------------------------------------------------------------------
// local_filter_path: conv1x1(64->64) -> relu -> conv1x1(64->49) -> normalize,
// all fused. One thread = one pixel.
// ---------------------------------------------------------------------------
__global__ __launch_bounds__(256, 1)
void lp_kernel(const float* __restrict__ kf,
               const float* __restrict__ w1, const float* __restrict__ b1,
               const float* __restrict__ w2, const float* __restrict__ b2,
               float* __restrict__ lp)
{
    __shared__ float s_w1[64*64];   // [ci][co]
    __shared__ float s_w2[64*52];   // [ci][k], row padded to 52
    __shared__ float s_b1[64];
    __shared__ float s_b2[49];
    const int tid = threadIdx.x;

    for (int i = tid; i < 64*64; i += 256) {
        int ci = i >> 6, co = i & 63;
        s_w1[i] = w1[co*64 + ci];
    }
    for (int i = tid; i < 64*49; i += 256) {
        int ci = i / 49, k = i - ci*49;
        s_w2[ci*52 + k] = w2[k*64 + ci];
    }
    if (tid < 64) s_b1[tid] = b1[tid];
    if (tid < 49) s_b2[tid] = b2[tid];
    __syncthreads();

    const int p  = blockIdx.x*256 + tid;   // 0..B*HW-1
    const int b  = p >> 14;                // /HW
    const int hw = p & (HWq-1);
    const float* kfp = kf + b*CHWq + hw;

    float h[64];
#pragma unroll
    for (int c = 0; c < 64; c++) h[c] = s_b1[c];
    for (int ci = 0; ci < 64; ci++) {
        float xv = kfp[ci*HWq];
#pragma unroll
        for (int co = 0; co < 64; co++)
            h[co] = fmaf(s_w1[ci*64 + co], xv, h[co]);
    }
#pragma unroll
    for (int c = 0; c < 64; c++) h[c] = fmaxf(h[c], 0.f);

    float o[TAPS];
#pragma unroll
    for (int k = 0; k < TAPS; k++) o[k] = s_b2[k];
    for (int ci = 0; ci < 64; ci++) {
        float hv = h[ci];
#pragma unroll
        for (int k = 0; k < TAPS; k++)
            o[k] = fmaf(s_w2[ci*52 + k], hv, o[k]);
    }
    float m = 0.f;
#pragma unroll
    for (int k = 0; k < TAPS; k++) m += o[k];
    m *= (1.0f/49.0f);

    float* lpp = lp + b*TAPS*HWq + hw;
#pragma unroll
    for (int k = 0; k < TAPS; k++)
        lpp[k*HWq] = o[k] - m + (1.0f/49.0f);
}

// ---------------------------------------------------------------------------
// dynamic 7x7 local conv + residual: out = x + sum_taps feat_shift * lp[tap].
// grid.z = B*8 : each block handles 8 channels.
// ---------------------------------------------------------------------------
#define LC_CG 8
#define LC_CPB (Cq/LC_CG)   // 8 channels per block
__global__ __launch_bounds__(256, 2)
void local_conv_kernel(const float* __restrict__ x, const float* __restrict__ feat,
                       const float* __restrict__ lp, float* __restrict__ out)
{
    __shared__ float s_f[22][24];
    const int bz = blockIdx.z;
    const int b  = bz >> 3;
    const int c0 = (bz & 7) * LC_CPB;
    const int x0 = blockIdx.x * TILE;
    const int y0 = blockIdx.y * TILE;
    const int tid = threadIdx.x;
    const int tx = tid & 15, ty = tid >> 4;
    const int y = y0 + ty, xx = x0 + tx;

    float kl[TAPS];
    const float* lpp = lp + b*TAPS*HWq + y*Wq + xx;
#pragma unroll
    for (int k = 0; k < TAPS; k++) kl[k] = lpp[k*HWq];

    const float* fb = feat + b*CHWq;
    const float* xb = x    + b*CHWq;
    float*       ob = out  + b*CHWq;

    for (int ci = 0; ci < LC_CPB; ci++) {
        const int c = c0 + ci;
        __syncthreads();
        for (int i = tid; i < 22*22; i += 256) {
            int r  = i / 22;
            int cc = i - r*22;
            int gy = y0 + r - 3, gx = x0 + cc - 3;
            float v = 0.f;
            if (gy >= 0 && gy < Hq && gx >= 0 && gx < Wq)
                v = fb[c*HWq + gy*Wq + gx];
            s_f[r][cc] = v;
        }
        __syncthreads();
        float acc = 0.f;
#pragma unroll
        for (int dy = 0; dy < KK; dy++)
#pragma unroll
            for (int dx = 0; dx < KK; dx++)
                acc = fmaf(s_f[ty+dy][tx+dx], kl[dy*KK+dx], acc);
        ob[c*HWq + y*Wq + xx] = xb[c*HWq + y*Wq + xx] + acc;
    }
}

// ---------------------------------------------------------------------------
extern "C" void kernel_launch(void* const* d_in, const int* in_sizes, int n_in,
                              void* d_out, int out_size)
{
    const float* x   = (const float*)d_in[0];
    const float* kf  = (const float*)d_in[1];
    const float* fw1 = (const float*)d_in[2];
    const float* fb1 = (const float*)d_in[3];
    const float* fw2 = (const float*)d_in[4];
    const float* fb2 = (const float*)d_in[5];
    const float* mw1 = (const float*)d_in[6];
    const float* mb1 = (const float*)d_in[7];
    const float* mw2 = (const float*)d_in[8];
    const float* mb2 = (const float*)d_in[9];
    const float* lw1 = (const float*)d_in[10];
    const float* lb1 = (const float*)d_in[11];
    const float* lw2 = (const float*)d_in[12];
    const float* lb2 = (const float*)d_in[13];
    float* out = (float*)d_out;

    float *b1p, *b2p, *b3p, *lpp;
    cudaGetSymbolAddress((void**)&b1p, g_buf1);
    cudaGetSymbolAddress((void**)&b2p, g_buf2);
    cudaGetSymbolAddress((void**)&b3p, g_buf3);
    cudaGetSymbolAddress((void**)&lpp, g_lp);

    dim3 cgrid(Wq/TILE, Hq/TILE, Bq);   // 8,8,4
    dim3 cblk(256);

    // local_filter_path first (independent of conv chain)
    lp_kernel<<<(Bq*HWq)/256, cblk>>>(kf, lw1, lb1, lw2, lb2, lpp);
    // feature_path: relu -> conv -> relu -> conv
    conv3x3_kernel<true,  true,  false><<<cgrid, cblk>>>(x,   fw1, fb1, nullptr, b1p);
    conv3x3_kernel<false, false, false><<<cgrid, cblk>>>(b1p, fw2, fb2, nullptr, b2p); // fp
    // multiplicative_path: conv -> relu -> conv, fused with fp multiply -> feat
    conv3x3_kernel<false, true,  false><<<cgrid, cblk>>>(kf,  mw1, mb1, nullptr, b1p);
    conv3x3_kernel<false, false, true ><<<cgrid, cblk>>>(b1p, mw2, mb2, b2p,     b3p); // feat
    // dynamic local conv + residual
    dim3 lgrid(Wq/TILE, Hq/TILE, Bq*LC_CG);
    local_conv_kernel<<<lgrid, cblk>>>(x, b3p, lpp, out);
}

// round 4
// speedup vs baseline: 1.7760x; 1.2078x over previous
#include <cuda_runtime.h>
#include <cuda_bf16.h>
#include <cstdint>

#define Bq 4
#define Cq 64
#define Hq 128
#define Wq 128
#define HWq (Hq*Wq)
#define CHWq (Cq*HWq)
#define KK 7
#define TAPS 49
#define WSZ (Cq*Cq*9)      // 36864 floats per 3x3 weight tensor

// scratch buffers (allocation-free rule: __device__ globals)
__device__ float g_rx  [Bq*Cq*Hq*Wq];   // relu(x)
__device__ float g_b1f [Bq*Cq*Hq*Wq];
__device__ float g_b1m [Bq*Cq*Hq*Wq];
__device__ float g_b2f [Bq*Cq*Hq*Wq];
__device__ float g_b2m [Bq*Cq*Hq*Wq];
__device__ float g_lp  [Bq*TAPS*Hq*Wq];
__device__ float g_wt  [4*WSZ];         // transposed weights [conv][(ci*9+tap)*64+co]

#define CI_CHUNK 4
#define NCHUNK (Cq/CI_CHUNK)   // 16
#define TILE 16
#define SROW 28

// ---------------------------------------------------------------------------
__device__ __forceinline__ void cp16(void* dst, const void* src) {
    unsigned d = (unsigned)__cvta_generic_to_shared(dst);
    asm volatile("cp.async.ca.shared.global [%0], [%1], 16;" :: "r"(d), "l"(src));
}
__device__ __forceinline__ void cp4z(void* dst, const void* src, unsigned sz) {
    unsigned d = (unsigned)__cvta_generic_to_shared(dst);
    asm volatile("cp.async.ca.shared.global [%0], [%1], 4, %2;" :: "r"(d), "l"(src), "r"(sz));
}
#define CP_COMMIT asm volatile("cp.async.commit_group;")
#define CP_WAIT0  asm volatile("cp.async.wait_group 0;")

// ---------------------------------------------------------------------------
// prep: relu(x) -> g_rx ; transpose 4 weight tensors -> g_wt
// ---------------------------------------------------------------------------
__global__ void prep_relu_kernel(const float* __restrict__ x, float* __restrict__ rx)
{
    int i = blockIdx.x*256 + threadIdx.x;
    float4 v = ((const float4*)x)[i];
    v.x = fmaxf(v.x, 0.f); v.y = fmaxf(v.y, 0.f);
    v.z = fmaxf(v.z, 0.f); v.w = fmaxf(v.w, 0.f);
    ((float4*)rx)[i] = v;
}
__global__ void prep_wt_kernel(const float* __restrict__ w0, const float* __restrict__ w1,
                               const float* __restrict__ w2, const float* __restrict__ w3,
                               float* __restrict__ wt)
{
    int i = blockIdx.x*256 + threadIdx.x;          // 0 .. 4*WSZ-1
    int conv = i / WSZ;
    int r    = i - conv*WSZ;                       // (ci*9+tap)*64+co
    int co   = r & 63;
    int rem  = r >> 6;                             // ci*9+tap
    int ci   = rem / 9;
    int tap  = rem - ci*9;
    const float* w = (conv == 0) ? w0 : (conv == 1) ? w1 : (conv == 2) ? w2 : w3;
    wt[i] = w[(co*Cq + ci)*9 + tap];
}

// ---------------------------------------------------------------------------
// conv3x3 pair kernel: grid.z in [0,8): z<4 -> path A (inA,wtA,biasA,outA),
// z>=4 -> path B. Per thread: 8 x-pixels x 8 output channels, f32x2 accs.
// cp.async ping-pong staging, 1 syncthreads per CI chunk.
// ---------------------------------------------------------------------------
template<bool RELU_OUT>
__global__ __launch_bounds__(256, 2)
void conv3x3_pair_kernel(const float* __restrict__ inA, const float* __restrict__ inB,
                         const float* __restrict__ wtA, const float* __restrict__ wtB,
                         const float* __restrict__ biasA, const float* __restrict__ biasB,
                         float* __restrict__ outA, float* __restrict__ outB)
{
    __shared__ float s_in[2][CI_CHUNK][18][SROW];
    __shared__ float s_w[2][CI_CHUNK*9*64];

    const int z  = blockIdx.z;
    const int b  = z & 3;
    const bool pathB = (z >= 4);
    const float* inb  = (pathB ? inB  : inA) + b*CHWq;
    const float* wt   =  pathB ? wtB  : wtA;
    const float* bias =  pathB ? biasB : biasA;
    float*       out  = (pathB ? outB : outA) + b*CHWq;

    const int x0 = blockIdx.x * TILE;
    const int y0 = blockIdx.y * TILE;
    const int tid = threadIdx.x;
    const int cg  = tid >> 5;          // warp-uniform channel group (8 ch)
    const int pg  = tid & 31;
    const int py  = pg >> 1;           // 0..15
    const int px8 = (pg & 1) << 3;     // 0 or 8

    // ---- staging lambda (cp.async) ----
    auto stage = [&](int buf, int cc) {
        // weights: CI_CHUNK*9*64 = 2304 floats = 576 float4, contiguous
        const float4* ws = (const float4*)(wt + cc*9*64);
        float* wd = s_w[buf];
#pragma unroll
        for (int i = 0; i < 3; i++) {
            int idx = tid + i*256;
            if (idx < 576) cp16(wd + idx*4, ws + idx);
        }
        // input: CI_CHUNK x 18 x 18 halo tile, 4B zfill copies
        for (int i = tid; i < CI_CHUNK*18*18; i += 256) {
            int ci_l = i / 324;
            int rem  = i - ci_l*324;
            int r    = rem / 18;
            int c    = rem - r*18;
            int gy = y0 + r - 1, gx = x0 + c - 1;
            bool ok = (gy >= 0) & (gy < Hq) & (gx >= 0) & (gx < Wq);
            const float* src = ok ? (inb + (cc+ci_l)*HWq + gy*Wq + gx) : inb;
            cp4z(&s_in[buf][ci_l][r][c], src, ok ? 4u : 0u);
        }
        CP_COMMIT;
    };

    unsigned long long acc[32];        // [px][k] : px*4+k
#pragma unroll
    for (int i = 0; i < 32; i++) acc[i] = 0ULL;

    stage(0, 0);

    for (int ch = 0; ch < NCHUNK; ch++) {
        const int buf = ch & 1;
        CP_WAIT0;
        __syncthreads();
        if (ch + 1 < NCHUNK) stage(buf ^ 1, (ch+1)*CI_CHUNK);

#pragma unroll
        for (int ci_l = 0; ci_l < CI_CHUNK; ci_l++) {
#pragma unroll
            for (int dy = 0; dy < 3; dy++) {
                const float4* ip = (const float4*)&s_in[buf][ci_l][py + dy][px8];
                float4 a0 = ip[0];
                float4 a1 = ip[1];
                float4 a2 = ip[2];
                unsigned long long d[10];
                {
                    unsigned int u;
                    u = __float_as_uint(a0.x); asm("mov.b64 %0,{%1,%1};" : "=l"(d[0]) : "r"(u));
                    u = __float_as_uint(a0.y); asm("mov.b64 %0,{%1,%1};" : "=l"(d[1]) : "r"(u));
                    u = __float_as_uint(a0.z); asm("mov.b64 %0,{%1,%1};" : "=l"(d[2]) : "r"(u));
                    u = __float_as_uint(a0.w); asm("mov.b64 %0,{%1,%1};" : "=l"(d[3]) : "r"(u));
                    u = __float_as_uint(a1.x); asm("mov.b64 %0,{%1,%1};" : "=l"(d[4]) : "r"(u));
                    u = __float_as_uint(a1.y); asm("mov.b64 %0,{%1,%1};" : "=l"(d[5]) : "r"(u));
                    u = __float_as_uint(a1.z); asm("mov.b64 %0,{%1,%1};" : "=l"(d[6]) : "r"(u));
                    u = __float_as_uint(a1.w); asm("mov.b64 %0,{%1,%1};" : "=l"(d[7]) : "r"(u));
                    u = __float_as_uint(a2.x); asm("mov.b64 %0,{%1,%1};" : "=l"(d[8]) : "r"(u));
                    u = __float_as_uint(a2.y); asm("mov.b64 %0,{%1,%1};" : "=l"(d[9]) : "r"(u));
                }
#pragma unroll
                for (int dx = 0; dx < 3; dx++) {
                    const ulonglong2* wv = (const ulonglong2*)
                        (s_w[buf] + (ci_l*9 + dy*3 + dx)*64 + (cg << 3));
                    ulonglong2 w0 = wv[0], w1 = wv[1];
                    unsigned long long w[4] = { w0.x, w0.y, w1.x, w1.y };
#pragma unroll
                    for (int i = 0; i < 8; i++) {
                        unsigned long long vd = d[i + dx];
#pragma unroll
                        for (int k = 0; k < 4; k++) {
                            asm("fma.rn.f32x2 %0, %1, %2, %0;"
                                : "+l"(acc[i*4 + k]) : "l"(w[k]), "l"(vd));
                        }
                    }
                }
            }
        }
        __syncthreads();
    }

    // epilogue: 8 channels x 8 px per thread; float4 stores
    const int y = y0 + py;
    const int xbase = x0 + px8;
    const int co0 = cg << 3;
    float* outp = out + y*Wq + xbase;
#pragma unroll
    for (int k = 0; k < 4; k++) {
        float lo[8], hi[8];
#pragma unroll
        for (int i = 0; i < 8; i++) {
            unsigned int u0, u1;
            asm("mov.b64 {%0,%1}, %2;" : "=r"(u0), "=r"(u1) : "l"(acc[i*4 + k]));
            lo[i] = __uint_as_float(u0);
            hi[i] = __uint_as_float(u1);
        }
        int cA = co0 + 2*k, cB = cA + 1;
        float bA = __ldg(bias + cA), bB = __ldg(bias + cB);
        float4 ra0, ra1, rb0, rb1;
        ra0.x = lo[0]+bA; ra0.y = lo[1]+bA; ra0.z = lo[2]+bA; ra0.w = lo[3]+bA;
        ra1.x = lo[4]+bA; ra1.y = lo[5]+bA; ra1.z = lo[6]+bA; ra1.w = lo[7]+bA;
        rb0.x = hi[0]+bB; rb0.y = hi[1]+bB; rb0.z = hi[2]+bB; rb0.w = hi[3]+bB;
        rb1.x = hi[4]+bB; rb1.y = hi[5]+bB; rb1.z = hi[6]+bB; rb1.w = hi[7]+bB;
        if (RELU_OUT) {
            ra0.x=fmaxf(ra0.x,0.f); ra0.y=fmaxf(ra0.y,0.f); ra0.z=fmaxf(ra0.z,0.f); ra0.w=fmaxf(ra0.w,0.f);
            ra1.x=fmaxf(ra1.x,0.f); ra1.y=fmaxf(ra1.y,0.f); ra1.z=fmaxf(ra1.z,0.f); ra1.w=fmaxf(ra1.w,0.f);
            rb0.x=fmaxf(rb0.x,0.f); rb0.y=fmaxf(rb0.y,0.f); rb0.z=fmaxf(rb0.z,0.f); rb0.w=fmaxf(rb0.w,0.f);
            rb1.x=fmaxf(rb1.x,0.f); rb1.y=fmaxf(rb1.y,0.f); rb1.z=fmaxf(rb1.z,0.f); rb1.w=fmaxf(rb1.w,0.f);
        }
        *(float4*)(outp + cA*HWq)     = ra0;
        *(float4*)(outp + cA*HWq + 4) = ra1;
        *(float4*)(outp + cB*HWq)     = rb0;
        *(float4*)(outp + cB*HWq + 4) = rb1;
    }
}

// ---------------------------------------------------------------------------
// local_filter_path: conv1x1(64->64) -> relu -> conv1x1(64->49) -> normalize
// ---------------------------------------------------------------------------
__global__ __launch_bounds__(256, 1)
void lp_kernel(const float* __restrict__ kf,
               const float* __restrict__ w1, const float* __restrict__ b1,
               const float* __restrict__ w2, const float* __restrict__ b2,
               float* __restrict__ lp)
{
    __shared__ float s_w1[64*64];   // [ci][co]
    __shared__ float s_w2[64*52];   // [ci][k], row padded to 52
    __shared__ float s_b1[64];
    __shared__ float s_b2[49];
    const int tid = threadIdx.x;

    for (int i = tid; i < 64*64; i += 256) {
        int ci = i >> 6, co = i & 63;
        s_w1[i] = w1[co*64 + ci];
    }
    for (int i = tid; i < 64*49; i += 256) {
        int ci = i / 49, k = i - ci*49;
        s_w2[ci*52 + k] = w2[k*64 + ci];
    }
    if (tid < 64) s_b1[tid] = b1[tid];
    if (tid < 49) s_b2[tid] = b2[tid];
    __syncthreads();

    const int p  = blockIdx.x*256 + tid;
    const int b  = p >> 14;
    const int hw = p & (HWq-1);
    const float* kfp = kf + b*CHWq + hw;

    float h[64];
#pragma unroll
    for (int c = 0; c < 64; c++) h[c] = s_b1[c];
    for (int ci = 0; ci < 64; ci++) {
        float xv = kfp[ci*HWq];
#pragma unroll
        for (int co = 0; co < 64; co++)
            h[co] = fmaf(s_w1[ci*64 + co], xv, h[co]);
    }
#pragma unroll
    for (int c = 0; c < 64; c++) h[c] = fmaxf(h[c], 0.f);

    float o[TAPS];
#pragma unroll
    for (int k = 0; k < TAPS; k++) o[k] = s_b2[k];
    for (int ci = 0; ci < 64; ci++) {
        float hv = h[ci];
#pragma unroll
        for (int k = 0; k < TAPS; k++)
            o[k] = fmaf(s_w2[ci*52 + k], hv, o[k]);
    }
    float m = 0.f;
#pragma unroll
    for (int k = 0; k < TAPS; k++) m += o[k];
    m *= (1.0f/49.0f);

    float* lpp = lp + b*TAPS*HWq + hw;
#pragma unroll
    for (int k = 0; k < TAPS; k++)
        lpp[k*HWq] = o[k] - m + (1.0f/49.0f);
}

// ---------------------------------------------------------------------------
// dynamic 7x7 local conv + residual, with on-the-fly feat = fp*mp product.
// grid.z = B*8 : each block handles 8 channels.
// ---------------------------------------------------------------------------
#define LC_CG 8
#define LC_CPB (Cq/LC_CG)
__global__ __launch_bounds__(256, 2)
void local_conv_kernel(const float* __restrict__ x,
                       const float* __restrict__ fp, const float* __restrict__ mp,
                       const float* __restrict__ lp, float* __restrict__ out)
{
    __shared__ float s_f[22][24];
    const int bz = blockIdx.z;
    const int b  = bz >> 3;
    const int c0 = (bz & 7) * LC_CPB;
    const int x0 = blockIdx.x * TILE;
    const int y0 = blockIdx.y * TILE;
    const int tid = threadIdx.x;
    const int tx = tid & 15, ty = tid >> 4;
    const int y = y0 + ty, xx = x0 + tx;

    float kl[TAPS];
    const float* lpp = lp + b*TAPS*HWq + y*Wq + xx;
#pragma unroll
    for (int k = 0; k < TAPS; k++) kl[k] = lpp[k*HWq];

    const float* fpb = fp + b*CHWq;
    const float* mpb = mp + b*CHWq;
    const float* xb  = x  + b*CHWq;
    float*       ob  = out + b*CHWq;

    for (int ci = 0; ci < LC_CPB; ci++) {
        const int c = c0 + ci;
        __syncthreads();
        for (int i = tid; i < 22*22; i += 256) {
            int r  = i / 22;
            int cc = i - r*22;
            int gy = y0 + r - 3, gx = x0 + cc - 3;
            float v = 0.f;
            if (gy >= 0 && gy < Hq && gx >= 0 && gx < Wq) {
                int off = c*HWq + gy*Wq + gx;
                v = fpb[off] * mpb[off];
            }
            s_f[r][cc] = v;
        }
        __syncthreads();
        float acc = 0.f;
#pragma unroll
        for (int dy = 0; dy < KK; dy++)
#pragma unroll
            for (int dx = 0; dx < KK; dx++)
                acc = fmaf(s_f[ty+dy][tx+dx], kl[dy*KK+dx], acc);
        ob[c*HWq + y*Wq + xx] = xb[c*HWq + y*Wq + xx] + acc;
    }
}

// ---------------------------------------------------------------------------
extern "C" void kernel_launch(void* const* d_in, const int* in_sizes, int n_in,
                              void* d_out, int out_size)
{
    const float* x   = (const float*)d_in[0];
    const float* kf  = (const float*)d_in[1];
    const float* fw1 = (const float*)d_in[2];
    const float* fb1 = (const float*)d_in[3];
    const float* fw2 = (const float*)d_in[4];
    const float* fb2 = (const float*)d_in[5];
    const float* mw1 = (const float*)d_in[6];
    const float* mb1 = (const float*)d_in[7];
    const float* mw2 = (const float*)d_in[8];
    const float* mb2 = (const float*)d_in[9];
    const float* lw1 = (const float*)d_in[10];
    const float* lb1 = (const float*)d_in[11];
    const float* lw2 = (const float*)d_in[12];
    const float* lb2 = (const float*)d_in[13];
    float* out = (float*)d_out;

    float *rxp, *b1fp, *b1mp, *b2fp, *b2mp, *lpp, *wtp;
    cudaGetSymbolAddress((void**)&rxp,  g_rx);
    cudaGetSymbolAddress((void**)&b1fp, g_b1f);
    cudaGetSymbolAddress((void**)&b1mp, g_b1m);
    cudaGetSymbolAddress((void**)&b2fp, g_b2f);
    cudaGetSymbolAddress((void**)&b2mp, g_b2m);
    cudaGetSymbolAddress((void**)&lpp,  g_lp);
    cudaGetSymbolAddress((void**)&wtp,  g_wt);

    dim3 cblk(256);

    // prep: relu(x), weight transposes
    prep_relu_kernel<<<(Bq*CHWq/4)/256, cblk>>>(x, rxp);
    prep_wt_kernel<<<(4*WSZ)/256, cblk>>>(fw1, fw2, mw1, mw2, wtp);
    // local_filter_path (independent)
    lp_kernel<<<(Bq*HWq)/256, cblk>>>(kf, lw1, lb1, lw2, lb2, lpp);

    dim3 cgrid(Wq/TILE, Hq/TILE, 2*Bq);   // 8,8,8 = 512 CTAs
    // stage 1: fp-conv1 (relu(x)) and mp-conv1 (kf), both relu_out
    conv3x3_pair_kernel<true><<<cgrid, cblk>>>(
        rxp, kf, wtp + 0*WSZ, wtp + 2*WSZ, fb1, mb1, b1fp, b1mp);
    // stage 2: fp-conv2 and mp-conv2, no relu
    conv3x3_pair_kernel<false><<<cgrid, cblk>>>(
        b1fp, b1mp, wtp + 1*WSZ, wtp + 3*WSZ, fb2, mb2, b2fp, b2mp);

    // dynamic local conv + residual (feat = fp*mp on the fly)
    dim3 lgrid(Wq/TILE, Hq/TILE, Bq*LC_CG);
    local_conv_kernel<<<lgrid, cblk>>>(x, b2fp, b2mp, lpp, out);
}